// round 13
// baseline (speedup 1.0000x reference)
#include <cuda_runtime.h>

#define NN 100000
#define EE 1000000
#define GG 2000
#define NGROUPS (NN / 4)          // 25000 node-groups (4 nodes each)
#define PBLOCKS 444               // 148 SMs x 3 blocks
#define PWARPS  (PBLOCKS * 8)     // 3552 persistent warps

// ---------------- scratch (device globals; no allocation allowed) ----------
__device__ float g_buf0[NN * 64];
__device__ float g_buf1[NN * 64];
__device__ int   g_rowptr[NN + 1];
__device__ int   g_cnt[NN];       // zero-init at load; cleanup re-zeros
__device__ int   g_cursor[NN];
__device__ int   g_srcperm[EE];
__device__ float g_eaperm[EE * 16];
__device__ float g_sums[GG * 64]; // zero-init at load; cleanup re-zeros
__device__ float g_cnts[GG];      // zero-init at load; cleanup re-zeros

typedef unsigned long long ull;

__device__ __forceinline__ ull pack2(float a, float b) {
    ull r; asm("mov.b64 %0, {%1,%2};" : "=l"(r) : "f"(a), "f"(b)); return r;
}
__device__ __forceinline__ void unpack2(ull v, float& a, float& b) {
    asm("mov.b64 {%0,%1}, %2;" : "=f"(a), "=f"(b) : "l"(v));
}
__device__ __forceinline__ void ffma2(ull& d, ull a, ull b) {
    asm("fma.rn.f32x2 %0, %1, %2, %0;" : "+l"(d) : "l"(a), "l"(b));
}
__device__ __forceinline__ void red2(float* p, float x, float y) {
    asm volatile("red.global.add.v2.f32 [%0], {%1,%2};"
                 :: "l"(p), "f"(x), "f"(y) : "memory");
}
__device__ __forceinline__ unsigned smem_u32(const void* p) {
    unsigned a;
    asm("{ .reg .u64 t; cvta.to.shared.u64 t, %1; cvt.u32.u64 %0, t; }"
        : "=r"(a) : "l"(p));
    return a;
}
#define CP_ASYNC16(saddr, gptr) \
    asm volatile("cp.async.cg.shared.global [%0], [%1], 16;" \
                 :: "r"(saddr), "l"(gptr) : "memory")
#define CP_COMMIT() asm volatile("cp.async.commit_group;" ::: "memory")
#define CP_WAIT1()  asm volatile("cp.async.wait_group 1;" ::: "memory")

// ============================ CSR build =====================================
__global__ void __launch_bounds__(256) count_kernel(const int* __restrict__ ei,
                                                    int* __restrict__ cnt) {
    int e = blockIdx.x * blockDim.x + threadIdx.x;
    if (e < EE) atomicAdd(&cnt[ei[EE + e]], 1);
}

__global__ void __launch_bounds__(1024) scan_kernel(const int* __restrict__ cnt,
                                                    int* __restrict__ rowptr,
                                                    int* __restrict__ cursor) {
    const int CH = 100;
    int tid = threadIdx.x;
    int base = tid * CH;
    int s = 0;
    for (int i = 0; i < CH; i += 4) {
        int idx = base + i;
        if (idx + 3 < NN) {
            int4 v = *(const int4*)(cnt + idx);
            s += v.x + v.y + v.z + v.w;
        } else {
            for (int t = 0; t < 4; t++)
                if (idx + t < NN) s += cnt[idx + t];
        }
    }
    __shared__ int sh[1024];
    sh[tid] = s;
    __syncthreads();
    for (int off = 1; off < 1024; off <<= 1) {
        int v = (tid >= off) ? sh[tid - off] : 0;
        __syncthreads();
        sh[tid] += v;
        __syncthreads();
    }
    int run = sh[tid] - s;
    for (int i = 0; i < CH; i += 4) {
        int idx = base + i;
        if (idx + 3 < NN) {
            int4 c = *(const int4*)(cnt + idx);
            int4 rp;
            rp.x = run;
            rp.y = run + c.x;
            rp.z = rp.y + c.y;
            rp.w = rp.z + c.z;
            *(int4*)(rowptr + idx) = rp;
            *(int4*)(cursor + idx) = rp;
            run = rp.w + c.w;
        } else {
            for (int t = 0; t < 4; t++) {
                int k2 = idx + t;
                if (k2 < NN) { rowptr[k2] = run; cursor[k2] = run; run += cnt[k2]; }
            }
        }
    }
    if (NN >= base && NN < base + CH) rowptr[NN] = run;
}

__global__ void __launch_bounds__(256) scatter_kernel(const int* __restrict__ ei,
                                                      const float* __restrict__ ea,
                                                      int* __restrict__ cursor,
                                                      int* __restrict__ srcperm,
                                                      float* __restrict__ eaperm) {
    int e = blockIdx.x * blockDim.x + threadIdx.x;
    if (e < EE) {
        int d = ei[EE + e];
        int pos = atomicAdd(&cursor[d], 1);
        srcperm[pos] = ei[e];
        const float4* src = (const float4*)(ea + (size_t)e * 16);
        float4* dst = (float4*)(eaperm + (size_t)pos * 16);
        float4 v0 = src[0], v1 = src[1], v2 = src[2], v3 = src[3];
        dst[0] = v0; dst[1] = v1; dst[2] = v2; dst[3] = v3;
    }
}

// ============================ fused layer ===================================
// PERSISTENT version of the measured-best (R10) layer: 444 blocks, each warp
// grid-strides over node-groups. Edge phase: 8-edge chunks, 2-buffer cp.async
// staging of edge features, batched x gathers. MLP: weights in shared, hdup.
template <bool LAST>
__global__ void __launch_bounds__(256, 3) layer_kernel(
    const float* __restrict__ x,
    const int* __restrict__ rowptr, const int* __restrict__ srcperm,
    const float* __restrict__ eaperm,
    const float* __restrict__ line,
    const float* __restrict__ W1, const float* __restrict__ b1,
    const float* __restrict__ W2, const float* __restrict__ b2,
    const float* __restrict__ epsp, int l,
    float* __restrict__ xout,
    const int* __restrict__ batch,
    float* __restrict__ sums, float* __restrict__ cnts)
{
    __shared__ ulonglong2 W1v[32 * 32];     // 16 KB
    __shared__ ulonglong2 W2v[32 * 32];     // 16 KB
    __shared__ ull hdup[8][4][32];          //  8 KB
    __shared__ ulonglong2 easm[8][2][32];   //  8 KB : [warp][buf][8 edges x 4 qwords]

    for (int i = threadIdx.x; i < 32 * 32; i += 256) {
        int kk = i >> 5, ln = i & 31;
        W1v[i] = make_ulonglong2(
            pack2(W1[(2 * kk) * 64 + 2 * ln],     W1[(2 * kk + 1) * 64 + 2 * ln]),
            pack2(W1[(2 * kk) * 64 + 2 * ln + 1], W1[(2 * kk + 1) * 64 + 2 * ln + 1]));
        W2v[i] = make_ulonglong2(
            pack2(W2[(2 * kk) * 64 + 2 * ln],     W2[(2 * kk + 1) * 64 + 2 * ln]),
            pack2(W2[(2 * kk) * 64 + 2 * ln + 1], W2[(2 * kk + 1) * 64 + 2 * ln + 1]));
    }
    __syncthreads();

    const int lane = threadIdx.x & 31;
    const int wib  = threadIdx.x >> 5;

    // Edge weights as k-pairs: wP for dim 2*lane, wQ for dim 2*lane+1.
    ull wP[8], wQ[8];
#pragma unroll
    for (int k = 0; k < 8; k++) {
        wP[k] = pack2(line[(2 * k) * 64 + 2 * lane],     line[(2 * k + 1) * 64 + 2 * lane]);
        wQ[k] = pack2(line[(2 * k) * 64 + 2 * lane + 1], line[(2 * k + 1) * 64 + 2 * lane + 1]);
    }

    const float epsv = 1.0f + epsp[l];
    const int gwarp = (blockIdx.x * 256 + threadIdx.x) >> 5;

    const char* eab = (const char*)eaperm;
    const unsigned easm_base = smem_u32(&easm[wib][0][0]) + lane * 16u;

    const float b1v0 = b1[2 * lane], b1v1 = b1[2 * lane + 1];
    const float b2v0 = b2[2 * lane], b2v1 = b2[2 * lane + 1];

    // ---- persistent loop over node-groups ----
    for (int grp = gwarp; grp < NGROUPS; grp += PWARPS) {
        const int n0 = grp * 4;

        const int r0   = rowptr[n0];
        const int bnd1 = rowptr[n0 + 1];
        const int bnd2 = rowptr[n0 + 2];
        const int bnd3 = rowptr[n0 + 3];
        const int r4   = rowptr[n0 + 4];

        int j = 0;
        int bnext = bnd1;
        float a0 = 0.f, a1 = 0.f;

        int cb = r0;
        int cnt = min(8, r4 - cb);

        // prologue: stage chunk 0 into buf 0
        if (cnt > 0 && lane < cnt * 4)
            CP_ASYNC16(easm_base, eab + (size_t)cb * 64 + lane * 16);
        CP_COMMIT();

        int buf = 0;
        while (cnt > 0) {
            // current chunk's src indices (overlaps with staging wait)
            int adr = cb + lane;
            adr = adr < r4 ? adr : r4 - 1;
            int sreg = __ldg(srcperm + adr);

            // prefetch chunk cb+8 into the other buffer
            const int cnt_n = min(8, r4 - (cb + 8));
            if (cnt_n > 0 && lane < cnt_n * 4)
                CP_ASYNC16(easm_base + (buf ^ 1) * 512u,
                           eab + (size_t)(cb + 8) * 64 + lane * 16);
            CP_COMMIT();

            CP_WAIT1();     // current buf's copies complete (next may pend)
            __syncwarp();   // make all lanes' copies visible

            // batched x gathers for the current chunk
            float2 xv[8];
#pragma unroll
            for (int t = 0; t < 8; t++) {
                int st = __shfl_sync(0xFFFFFFFFu, sreg, t);
                if (t < cnt)
                    xv[t] = __ldg((const float2*)(x + (size_t)st * 64 + lane * 2));
            }

            // compute 8 edges from easm[wib][buf]
#pragma unroll
            for (int t = 0; t < 8; t++) {
                if (t >= cnt) break;                 // warp-uniform
                const int p = cb + t;
                while (p >= bnext) {                 // warp-uniform, rare
                    float2 xs = *(const float2*)(x + (size_t)(n0 + j) * 64 + lane * 2);
                    hdup[wib][j][lane] = pack2(fmaf(epsv, xs.x, a0), fmaf(epsv, xs.y, a1));
                    a0 = 0.f; a1 = 0.f;
                    j++;
                    bnext = (j == 1) ? bnd2 : (j == 2) ? bnd3 : r4;
                }
                ulonglong2 E0 = easm[wib][buf][4 * t + 0];
                ulonglong2 E1 = easm[wib][buf][4 * t + 1];
                ulonglong2 E2 = easm[wib][buf][4 * t + 2];
                ulonglong2 E3 = easm[wib][buf][4 * t + 3];
                ull acP = 0ull, acQ = 0ull;
                ffma2(acP, E0.x, wP[0]); ffma2(acQ, E0.x, wQ[0]);
                ffma2(acP, E0.y, wP[1]); ffma2(acQ, E0.y, wQ[1]);
                ffma2(acP, E1.x, wP[2]); ffma2(acQ, E1.x, wQ[2]);
                ffma2(acP, E1.y, wP[3]); ffma2(acQ, E1.y, wQ[3]);
                ffma2(acP, E2.x, wP[4]); ffma2(acQ, E2.x, wQ[4]);
                ffma2(acP, E2.y, wP[5]); ffma2(acQ, E2.y, wQ[5]);
                ffma2(acP, E3.x, wP[6]); ffma2(acQ, E3.x, wQ[6]);
                ffma2(acP, E3.y, wP[7]); ffma2(acQ, E3.y, wQ[7]);
                float pa, pb, qa, qb;
                unpack2(acP, pa, pb);
                unpack2(acQ, qa, qb);
                float m0 = (pa + xv[t].x) + pb;
                float m1 = (qa + xv[t].y) + qb;
                a0 += fmaxf(m0, 0.f);
                a1 += fmaxf(m1, 0.f);
            }
            __syncwarp();   // all lanes done reading buf before re-staging

            buf ^= 1;
            cb += 8;
            cnt = cnt_n;
        }
        while (j < 4) {   // flush remaining nodes (incl. zero-degree)
            float2 xs = *(const float2*)(x + (size_t)(n0 + j) * 64 + lane * 2);
            hdup[wib][j][lane] = pack2(fmaf(epsv, xs.x, a0), fmaf(epsv, xs.y, a1));
            a0 = 0.f; a1 = 0.f;
            j++;
        }
        __syncwarp();

        // ---- MLP matmul 1 (bias folded into acc.lo) ----
        ull accP[4], accQ[4];
#pragma unroll
        for (int jj = 0; jj < 4; jj++) {
            accP[jj] = pack2(b1v0, 0.f);
            accQ[jj] = pack2(b1v1, 0.f);
        }
#pragma unroll 8
        for (int kk = 0; kk < 32; kk++) {
            ulonglong2 wv = W1v[kk * 32 + lane];
#pragma unroll
            for (int jj = 0; jj < 4; jj++) {
                ull hp = hdup[wib][jj][kk];
                ffma2(accP[jj], hp, wv.x);
                ffma2(accQ[jj], hp, wv.y);
            }
        }
        __syncwarp();
#pragma unroll
        for (int jj = 0; jj < 4; jj++) {
            float pa, pb, qa, qb;
            unpack2(accP[jj], pa, pb);
            unpack2(accQ[jj], qa, qb);
            float y0 = fmaxf(pa + pb, 0.f);
            float y1 = fmaxf(qa + qb, 0.f);
            hdup[wib][jj][lane] = pack2(y0, y1);
            accP[jj] = pack2(b2v0, 0.f);
            accQ[jj] = pack2(b2v1, 0.f);
        }
        __syncwarp();

        // ---- MLP matmul 2 ----
#pragma unroll 8
        for (int kk = 0; kk < 32; kk++) {
            ulonglong2 wv = W2v[kk * 32 + lane];
#pragma unroll
            for (int jj = 0; jj < 4; jj++) {
                ull hp = hdup[wib][jj][kk];
                ffma2(accP[jj], hp, wv.x);
                ffma2(accQ[jj], hp, wv.y);
            }
        }

#pragma unroll
        for (int jj = 0; jj < 4; jj++) {
            float pa, pb, qa, qb;
            unpack2(accP[jj], pa, pb);
            unpack2(accQ[jj], qa, qb);
            float y0 = fmaxf(pa + pb, 0.f);
            float y1 = fmaxf(qa + qb, 0.f);
            if (!LAST) {
                *(float2*)(xout + (size_t)(n0 + jj) * 64 + lane * 2) = make_float2(y0, y1);
            } else {
                int g = batch[n0 + jj];
                red2(sums + (size_t)g * 64 + lane * 2, y0, y1);
                if (lane == 0) atomicAdd(cnts + g, 1.0f);
            }
        }
        __syncwarp();   // hdup reused by the next group
    }
}

// ============================ head ==========================================
__global__ void __launch_bounds__(256) head_kernel(
    const float* __restrict__ sums, const float* __restrict__ cnts,
    const float* __restrict__ t_cond,
    const float* __restrict__ hW1, const float* __restrict__ hb1,
    const float* __restrict__ hW2, const float* __restrict__ hb2,
    float* __restrict__ out)
{
    const int lane = threadIdx.x & 31;
    const int g    = (blockIdx.x * blockDim.x + threadIdx.x) >> 5;
    if (g >= GG) return;

    float c  = fmaxf(cnts[g], 1.0f);
    float p0 = sums[(size_t)g * 64 + lane] / c;
    float p1 = sums[(size_t)g * 64 + lane + 32] / c;

    float acc0 = hb1[lane], acc1 = hb1[lane + 32];
    for (int k = 0; k < 32; k++) {
        float a = __shfl_sync(0xFFFFFFFFu, p0, k);
        acc0 = fmaf(a, hW1[k * 64 + lane],      acc0);
        acc1 = fmaf(a, hW1[k * 64 + lane + 32], acc1);
    }
    for (int k = 0; k < 32; k++) {
        float a = __shfl_sync(0xFFFFFFFFu, p1, k);
        acc0 = fmaf(a, hW1[(k + 32) * 64 + lane],      acc0);
        acc1 = fmaf(a, hW1[(k + 32) * 64 + lane + 32], acc1);
    }
    float t = t_cond[g];
    acc0 = fmaf(t, hW1[64 * 64 + lane],      acc0);
    acc1 = fmaf(t, hW1[64 * 64 + lane + 32], acc1);

    acc0 = fmaxf(acc0, 0.f);
    acc1 = fmaxf(acc1, 0.f);

    float r = acc0 * hW2[lane] + acc1 * hW2[lane + 32];
#pragma unroll
    for (int o = 16; o; o >>= 1) r += __shfl_xor_sync(0xFFFFFFFFu, r, o);
    if (lane == 0) out[g] = r + hb2[0];
}

// Trailing cleanup: re-zero accumulators for the next execution.
__global__ void __launch_bounds__(256) cleanup_kernel(int* __restrict__ cnt,
                                                      float* __restrict__ sums,
                                                      float* __restrict__ cnts) {
    int i = blockIdx.x * blockDim.x + threadIdx.x;
    if (i < NN) cnt[i] = 0;
    if (i < GG * 64) sums[i] = 0.f;
    if (i < GG) cnts[i] = 0.f;
}

// ============================================================================
extern "C" void kernel_launch(void* const* d_in, const int* in_sizes, int n_in,
                              void* d_out, int out_size)
{
    const float* x      = (const float*)d_in[0];
    const int*   ei     = (const int*)  d_in[1];
    const float* ea     = (const float*)d_in[2];
    const int*   batch  = (const int*)  d_in[3];
    const float* t_cond = (const float*)d_in[4];
    const float* lin_e  = (const float*)d_in[5];
    const float* W1     = (const float*)d_in[6];
    const float* b1     = (const float*)d_in[7];
    const float* W2     = (const float*)d_in[8];
    const float* b2     = (const float*)d_in[9];
    const float* eps    = (const float*)d_in[10];
    const float* hW1    = (const float*)d_in[11];
    const float* hb1    = (const float*)d_in[12];
    const float* hW2    = (const float*)d_in[13];
    const float* hb2    = (const float*)d_in[14];
    float* out = (float*)d_out;

    float *buf0, *buf1, *eaperm, *sums, *cnts;
    int *rowptr, *cnt, *cursor, *srcperm;
    cudaGetSymbolAddress((void**)&buf0, g_buf0);
    cudaGetSymbolAddress((void**)&buf1, g_buf1);
    cudaGetSymbolAddress((void**)&rowptr, g_rowptr);
    cudaGetSymbolAddress((void**)&cnt, g_cnt);
    cudaGetSymbolAddress((void**)&cursor, g_cursor);
    cudaGetSymbolAddress((void**)&srcperm, g_srcperm);
    cudaGetSymbolAddress((void**)&eaperm, g_eaperm);
    cudaGetSymbolAddress((void**)&sums, g_sums);
    cudaGetSymbolAddress((void**)&cnts, g_cnts);

    // ---- CSR build ----
    count_kernel<<<(EE + 255) / 256, 256>>>(ei, cnt);
    scan_kernel<<<1, 1024>>>(cnt, rowptr, cursor);
    scatter_kernel<<<(EE + 255) / 256, 256>>>(ei, ea, cursor, srcperm, eaperm);

    // ---- 4 fused layers (persistent grid) ----
    float* bufs[2] = {buf0, buf1};
    const float* cur = x;
    for (int l = 0; l < 3; l++) {
        float* nxt = bufs[l & 1];
        layer_kernel<false><<<PBLOCKS, 256>>>(
            cur, rowptr, srcperm, eaperm,
            lin_e + (size_t)l * 16 * 64,
            W1 + (size_t)l * 64 * 64, b1 + (size_t)l * 64,
            W2 + (size_t)l * 64 * 64, b2 + (size_t)l * 64,
            eps, l, nxt, batch, sums, cnts);
        cur = nxt;
    }
    layer_kernel<true><<<PBLOCKS, 256>>>(
        cur, rowptr, srcperm, eaperm,
        lin_e + (size_t)3 * 16 * 64,
        W1 + (size_t)3 * 64 * 64, b1 + (size_t)3 * 64,
        W2 + (size_t)3 * 64 * 64, b2 + (size_t)3 * 64,
        eps, 3, nullptr, batch, sums, cnts);

    head_kernel<<<(GG + 7) / 8, 256>>>(sums, cnts, t_cond, hW1, hb1, hW2, hb2, out);
    cleanup_kernel<<<(GG * 64 + 255) / 256, 256>>>(cnt, sums, cnts);
}

// round 14
// speedup vs baseline: 1.0846x; 1.0846x over previous
#include <cuda_runtime.h>

#define NN 100000
#define EE 1000000
#define GG 2000

// ---------------- scratch (device globals; no allocation allowed) ----------
__device__ float g_buf0[NN * 64];
__device__ float g_buf1[NN * 64];
__device__ int   g_rowptr[NN + 1];
__device__ int   g_cnt[NN];       // zero-init at load; scan re-zeros after use
__device__ int   g_cursor[NN];
__device__ int   g_srcperm[EE];
__device__ float g_eaperm[EE * 16];
__device__ float g_sums[GG * 64]; // zero-init at load; head re-zeros after use
__device__ float g_cnts[GG];      // zero-init at load; head re-zeros after use

typedef unsigned long long ull;

__device__ __forceinline__ ull pack2(float a, float b) {
    ull r; asm("mov.b64 %0, {%1,%2};" : "=l"(r) : "f"(a), "f"(b)); return r;
}
__device__ __forceinline__ void unpack2(ull v, float& a, float& b) {
    asm("mov.b64 {%0,%1}, %2;" : "=f"(a), "=f"(b) : "l"(v));
}
__device__ __forceinline__ void ffma2(ull& d, ull a, ull b) {
    asm("fma.rn.f32x2 %0, %1, %2, %0;" : "+l"(d) : "l"(a), "l"(b));
}
__device__ __forceinline__ void red2(float* p, float x, float y) {
    asm volatile("red.global.add.v2.f32 [%0], {%1,%2};"
                 :: "l"(p), "f"(x), "f"(y) : "memory");
}
__device__ __forceinline__ unsigned smem_u32(const void* p) {
    unsigned a;
    asm("{ .reg .u64 t; cvta.to.shared.u64 t, %1; cvt.u32.u64 %0, t; }"
        : "=r"(a) : "l"(p));
    return a;
}
#define CP_ASYNC16(saddr, gptr) \
    asm volatile("cp.async.cg.shared.global [%0], [%1], 16;" \
                 :: "r"(saddr), "l"(gptr) : "memory")
#define CP_COMMIT() asm volatile("cp.async.commit_group;" ::: "memory")
#define CP_WAIT1()  asm volatile("cp.async.wait_group 1;" ::: "memory")

// ============================ CSR build =====================================
__global__ void __launch_bounds__(256) count_kernel(const int* __restrict__ ei,
                                                    int* __restrict__ cnt) {
    int e = blockIdx.x * blockDim.x + threadIdx.x;
    if (e < EE) atomicAdd(&cnt[ei[EE + e]], 1);
}

// Exclusive scan over cnt -> rowptr[NN+1] and cursor; cnt re-zeroed after use.
__global__ void __launch_bounds__(1024) scan_kernel(int* __restrict__ cnt,
                                                    int* __restrict__ rowptr,
                                                    int* __restrict__ cursor) {
    const int CH = 100;
    int tid = threadIdx.x;
    int base = tid * CH;
    int s = 0;
    for (int i = 0; i < CH; i += 4) {
        int idx = base + i;
        if (idx + 3 < NN) {
            int4 v = *(const int4*)(cnt + idx);
            s += v.x + v.y + v.z + v.w;
        } else {
            for (int t = 0; t < 4; t++)
                if (idx + t < NN) s += cnt[idx + t];
        }
    }
    __shared__ int sh[1024];
    sh[tid] = s;
    __syncthreads();
    for (int off = 1; off < 1024; off <<= 1) {
        int v = (tid >= off) ? sh[tid - off] : 0;
        __syncthreads();
        sh[tid] += v;
        __syncthreads();
    }
    int run = sh[tid] - s;
    const int4 zero4 = make_int4(0, 0, 0, 0);
    for (int i = 0; i < CH; i += 4) {
        int idx = base + i;
        if (idx + 3 < NN) {
            int4 c = *(const int4*)(cnt + idx);
            int4 rp;
            rp.x = run;
            rp.y = run + c.x;
            rp.z = rp.y + c.y;
            rp.w = rp.z + c.z;
            *(int4*)(rowptr + idx) = rp;
            *(int4*)(cursor + idx) = rp;
            *(int4*)(cnt + idx) = zero4;      // reset for next execution
            run = rp.w + c.w;
        } else {
            for (int t = 0; t < 4; t++) {
                int k2 = idx + t;
                if (k2 < NN) {
                    rowptr[k2] = run; cursor[k2] = run;
                    run += cnt[k2]; cnt[k2] = 0;
                }
            }
        }
    }
    if (NN >= base && NN < base + CH) rowptr[NN] = run;
}

__global__ void __launch_bounds__(256) scatter_kernel(const int* __restrict__ ei,
                                                      const float* __restrict__ ea,
                                                      int* __restrict__ cursor,
                                                      int* __restrict__ srcperm,
                                                      float* __restrict__ eaperm) {
    int e = blockIdx.x * blockDim.x + threadIdx.x;
    if (e < EE) {
        int d = ei[EE + e];
        int pos = atomicAdd(&cursor[d], 1);
        srcperm[pos] = ei[e];
        const float4* src = (const float4*)(ea + (size_t)e * 16);
        float4* dst = (float4*)(eaperm + (size_t)pos * 16);
        float4 v0 = src[0], v1 = src[1], v2 = src[2], v3 = src[3];
        dst[0] = v0; dst[1] = v1; dst[2] = v2; dst[3] = v3;
    }
}

// ============================ fused layer ===================================
// Measured-best (R10) edge loop: 8-edge chunks, 2-buffer cp.async staging of
// edge features, batched x gathers. MLP uses transposed hd[warp][kpair][node]
// so each kk step is 2 broadcast LDS.128 + 8 FFMA2.
template <bool LAST>
__global__ void __launch_bounds__(256, 3) layer_kernel(
    const float* __restrict__ x,
    const int* __restrict__ rowptr, const int* __restrict__ srcperm,
    const float* __restrict__ eaperm,
    const float* __restrict__ line,
    const float* __restrict__ W1, const float* __restrict__ b1,
    const float* __restrict__ W2, const float* __restrict__ b2,
    const float* __restrict__ epsp, int l,
    float* __restrict__ xout,
    const int* __restrict__ batch,
    float* __restrict__ sums, float* __restrict__ cnts)
{
    __shared__ ulonglong2 W1v[32 * 32];     // 16 KB
    __shared__ ulonglong2 W2v[32 * 32];     // 16 KB
    __shared__ ull hd[8][32][4];            //  8 KB : [warp][dim-pair][node]
    __shared__ ulonglong2 easm[8][2][32];   //  8 KB : [warp][buf][8 edges x 4 qwords]

    for (int i = threadIdx.x; i < 32 * 32; i += 256) {
        int kk = i >> 5, ln = i & 31;
        W1v[i] = make_ulonglong2(
            pack2(W1[(2 * kk) * 64 + 2 * ln],     W1[(2 * kk + 1) * 64 + 2 * ln]),
            pack2(W1[(2 * kk) * 64 + 2 * ln + 1], W1[(2 * kk + 1) * 64 + 2 * ln + 1]));
        W2v[i] = make_ulonglong2(
            pack2(W2[(2 * kk) * 64 + 2 * ln],     W2[(2 * kk + 1) * 64 + 2 * ln]),
            pack2(W2[(2 * kk) * 64 + 2 * ln + 1], W2[(2 * kk + 1) * 64 + 2 * ln + 1]));
    }
    __syncthreads();

    const int lane = threadIdx.x & 31;
    const int wib  = threadIdx.x >> 5;

    // Edge weights as k-pairs: wP for dim 2*lane, wQ for dim 2*lane+1.
    ull wP[8], wQ[8];
#pragma unroll
    for (int k = 0; k < 8; k++) {
        wP[k] = pack2(line[(2 * k) * 64 + 2 * lane],     line[(2 * k + 1) * 64 + 2 * lane]);
        wQ[k] = pack2(line[(2 * k) * 64 + 2 * lane + 1], line[(2 * k + 1) * 64 + 2 * lane + 1]);
    }

    const float epsv = 1.0f + epsp[l];
    const int warp = (blockIdx.x * 256 + threadIdx.x) >> 5;
    const int n0 = warp * 4;

    const int r0   = rowptr[n0];
    const int bnd1 = rowptr[n0 + 1];
    const int bnd2 = rowptr[n0 + 2];
    const int bnd3 = rowptr[n0 + 3];
    const int r4   = rowptr[n0 + 4];

    const char* eab = (const char*)eaperm;
    const unsigned easm_base = smem_u32(&easm[wib][0][0]) + lane * 16u;

    int j = 0;
    int bnext = bnd1;
    float a0 = 0.f, a1 = 0.f;

    int cb = r0;
    int cnt = min(8, r4 - cb);

    // prologue: stage chunk 0 into buf 0
    if (cnt > 0 && lane < cnt * 4)
        CP_ASYNC16(easm_base, eab + (size_t)cb * 64 + lane * 16);
    CP_COMMIT();

    int buf = 0;
    while (cnt > 0) {
        // current chunk's src indices (overlaps with staging wait)
        int adr = cb + lane;
        adr = adr < r4 ? adr : r4 - 1;
        int sreg = __ldg(srcperm + adr);

        // prefetch chunk cb+8 into the other buffer (no registers consumed)
        const int cnt_n = min(8, r4 - (cb + 8));
        if (cnt_n > 0 && lane < cnt_n * 4)
            CP_ASYNC16(easm_base + (buf ^ 1) * 512u,
                       eab + (size_t)(cb + 8) * 64 + lane * 16);
        CP_COMMIT();

        CP_WAIT1();     // current buf's copies complete (next chunk may pend)
        __syncwarp();   // make all lanes' copies visible

        // batched x gathers for the current chunk
        float2 xv[8];
#pragma unroll
        for (int t = 0; t < 8; t++) {
            int st = __shfl_sync(0xFFFFFFFFu, sreg, t);
            if (t < cnt)
                xv[t] = __ldg((const float2*)(x + (size_t)st * 64 + lane * 2));
        }

        // compute 8 edges from easm[wib][buf]
#pragma unroll
        for (int t = 0; t < 8; t++) {
            if (t >= cnt) break;                 // warp-uniform
            const int p = cb + t;
            while (p >= bnext) {                 // warp-uniform, rare
                float2 xs = *(const float2*)(x + (size_t)(n0 + j) * 64 + lane * 2);
                hd[wib][lane][j] = pack2(fmaf(epsv, xs.x, a0), fmaf(epsv, xs.y, a1));
                a0 = 0.f; a1 = 0.f;
                j++;
                bnext = (j == 1) ? bnd2 : (j == 2) ? bnd3 : r4;
            }
            ulonglong2 E0 = easm[wib][buf][4 * t + 0];
            ulonglong2 E1 = easm[wib][buf][4 * t + 1];
            ulonglong2 E2 = easm[wib][buf][4 * t + 2];
            ulonglong2 E3 = easm[wib][buf][4 * t + 3];
            ull acP = 0ull, acQ = 0ull;
            ffma2(acP, E0.x, wP[0]); ffma2(acQ, E0.x, wQ[0]);
            ffma2(acP, E0.y, wP[1]); ffma2(acQ, E0.y, wQ[1]);
            ffma2(acP, E1.x, wP[2]); ffma2(acQ, E1.x, wQ[2]);
            ffma2(acP, E1.y, wP[3]); ffma2(acQ, E1.y, wQ[3]);
            ffma2(acP, E2.x, wP[4]); ffma2(acQ, E2.x, wQ[4]);
            ffma2(acP, E2.y, wP[5]); ffma2(acQ, E2.y, wQ[5]);
            ffma2(acP, E3.x, wP[6]); ffma2(acQ, E3.x, wQ[6]);
            ffma2(acP, E3.y, wP[7]); ffma2(acQ, E3.y, wQ[7]);
            float pa, pb, qa, qb;
            unpack2(acP, pa, pb);
            unpack2(acQ, qa, qb);
            float m0 = (pa + xv[t].x) + pb;
            float m1 = (qa + xv[t].y) + qb;
            a0 += fmaxf(m0, 0.f);
            a1 += fmaxf(m1, 0.f);
        }
        __syncwarp();   // all lanes done reading buf before it is re-staged

        buf ^= 1;
        cb += 8;
        cnt = cnt_n;
    }
    while (j < 4) {   // flush remaining nodes (incl. zero-degree)
        float2 xs = *(const float2*)(x + (size_t)(n0 + j) * 64 + lane * 2);
        hd[wib][lane][j] = pack2(fmaf(epsv, xs.x, a0), fmaf(epsv, xs.y, a1));
        a0 = 0.f; a1 = 0.f;
        j++;
    }
    __syncwarp();

    const float b1v0 = b1[2 * lane], b1v1 = b1[2 * lane + 1];
    const float b2v0 = b2[2 * lane], b2v1 = b2[2 * lane + 1];

    // ---- MLP matmul 1 (bias folded into acc.lo; broadcast LDS.128) ----
    ull accP[4], accQ[4];
#pragma unroll
    for (int jj = 0; jj < 4; jj++) {
        accP[jj] = pack2(b1v0, 0.f);
        accQ[jj] = pack2(b1v1, 0.f);
    }
#pragma unroll 8
    for (int kk = 0; kk < 32; kk++) {
        ulonglong2 wv  = W1v[kk * 32 + lane];
        ulonglong2 h01 = *(const ulonglong2*)&hd[wib][kk][0];
        ulonglong2 h23 = *(const ulonglong2*)&hd[wib][kk][2];
        ffma2(accP[0], h01.x, wv.x); ffma2(accQ[0], h01.x, wv.y);
        ffma2(accP[1], h01.y, wv.x); ffma2(accQ[1], h01.y, wv.y);
        ffma2(accP[2], h23.x, wv.x); ffma2(accQ[2], h23.x, wv.y);
        ffma2(accP[3], h23.y, wv.x); ffma2(accQ[3], h23.y, wv.y);
    }
    __syncwarp();
    {
        ull y01[4];
#pragma unroll
        for (int jj = 0; jj < 4; jj++) {
            float pa, pb, qa, qb;
            unpack2(accP[jj], pa, pb);
            unpack2(accQ[jj], qa, qb);
            y01[jj] = pack2(fmaxf(pa + pb, 0.f), fmaxf(qa + qb, 0.f));
            accP[jj] = pack2(b2v0, 0.f);
            accQ[jj] = pack2(b2v1, 0.f);
        }
        *(ulonglong2*)&hd[wib][lane][0] = make_ulonglong2(y01[0], y01[1]);
        *(ulonglong2*)&hd[wib][lane][2] = make_ulonglong2(y01[2], y01[3]);
    }
    __syncwarp();

    // ---- MLP matmul 2 ----
#pragma unroll 8
    for (int kk = 0; kk < 32; kk++) {
        ulonglong2 wv  = W2v[kk * 32 + lane];
        ulonglong2 h01 = *(const ulonglong2*)&hd[wib][kk][0];
        ulonglong2 h23 = *(const ulonglong2*)&hd[wib][kk][2];
        ffma2(accP[0], h01.x, wv.x); ffma2(accQ[0], h01.x, wv.y);
        ffma2(accP[1], h01.y, wv.x); ffma2(accQ[1], h01.y, wv.y);
        ffma2(accP[2], h23.x, wv.x); ffma2(accQ[2], h23.x, wv.y);
        ffma2(accP[3], h23.y, wv.x); ffma2(accQ[3], h23.y, wv.y);
    }

#pragma unroll
    for (int jj = 0; jj < 4; jj++) {
        float pa, pb, qa, qb;
        unpack2(accP[jj], pa, pb);
        unpack2(accQ[jj], qa, qb);
        float y0 = fmaxf(pa + pb, 0.f);
        float y1 = fmaxf(qa + qb, 0.f);
        if (!LAST) {
            *(float2*)(xout + (size_t)(n0 + jj) * 64 + lane * 2) = make_float2(y0, y1);
        } else {
            int g = batch[n0 + jj];
            red2(sums + (size_t)g * 64 + lane * 2, y0, y1);
            if (lane == 0) atomicAdd(cnts + g, 1.0f);
        }
    }
}

// ============================ head ==========================================
// Also re-zeros sums/cnts for the next execution (stream-ordered, safe).
__global__ void __launch_bounds__(256) head_kernel(
    float* __restrict__ sums, float* __restrict__ cnts,
    const float* __restrict__ t_cond,
    const float* __restrict__ hW1, const float* __restrict__ hb1,
    const float* __restrict__ hW2, const float* __restrict__ hb2,
    float* __restrict__ out)
{
    const int lane = threadIdx.x & 31;
    const int g    = (blockIdx.x * blockDim.x + threadIdx.x) >> 5;
    if (g >= GG) return;

    float c  = fmaxf(cnts[g], 1.0f);
    float p0 = sums[(size_t)g * 64 + lane] / c;
    float p1 = sums[(size_t)g * 64 + lane + 32] / c;

    // reset accumulators for the next execution
    sums[(size_t)g * 64 + lane] = 0.f;
    sums[(size_t)g * 64 + lane + 32] = 0.f;
    if (lane == 0) cnts[g] = 0.f;

    float acc0 = hb1[lane], acc1 = hb1[lane + 32];
    for (int k = 0; k < 32; k++) {
        float a = __shfl_sync(0xFFFFFFFFu, p0, k);
        acc0 = fmaf(a, hW1[k * 64 + lane],      acc0);
        acc1 = fmaf(a, hW1[k * 64 + lane + 32], acc1);
    }
    for (int k = 0; k < 32; k++) {
        float a = __shfl_sync(0xFFFFFFFFu, p1, k);
        acc0 = fmaf(a, hW1[(k + 32) * 64 + lane],      acc0);
        acc1 = fmaf(a, hW1[(k + 32) * 64 + lane + 32], acc1);
    }
    float t = t_cond[g];
    acc0 = fmaf(t, hW1[64 * 64 + lane],      acc0);
    acc1 = fmaf(t, hW1[64 * 64 + lane + 32], acc1);

    acc0 = fmaxf(acc0, 0.f);
    acc1 = fmaxf(acc1, 0.f);

    float r = acc0 * hW2[lane] + acc1 * hW2[lane + 32];
#pragma unroll
    for (int o = 16; o; o >>= 1) r += __shfl_xor_sync(0xFFFFFFFFu, r, o);
    if (lane == 0) out[g] = r + hb2[0];
}

// ============================================================================
extern "C" void kernel_launch(void* const* d_in, const int* in_sizes, int n_in,
                              void* d_out, int out_size)
{
    const float* x      = (const float*)d_in[0];
    const int*   ei     = (const int*)  d_in[1];
    const float* ea     = (const float*)d_in[2];
    const int*   batch  = (const int*)  d_in[3];
    const float* t_cond = (const float*)d_in[4];
    const float* lin_e  = (const float*)d_in[5];
    const float* W1     = (const float*)d_in[6];
    const float* b1     = (const float*)d_in[7];
    const float* W2     = (const float*)d_in[8];
    const float* b2     = (const float*)d_in[9];
    const float* eps    = (const float*)d_in[10];
    const float* hW1    = (const float*)d_in[11];
    const float* hb1    = (const float*)d_in[12];
    const float* hW2    = (const float*)d_in[13];
    const float* hb2    = (const float*)d_in[14];
    float* out = (float*)d_out;

    float *buf0, *buf1, *eaperm, *sums, *cnts;
    int *rowptr, *cnt, *cursor, *srcperm;
    cudaGetSymbolAddress((void**)&buf0, g_buf0);
    cudaGetSymbolAddress((void**)&buf1, g_buf1);
    cudaGetSymbolAddress((void**)&rowptr, g_rowptr);
    cudaGetSymbolAddress((void**)&cnt, g_cnt);
    cudaGetSymbolAddress((void**)&cursor, g_cursor);
    cudaGetSymbolAddress((void**)&srcperm, g_srcperm);
    cudaGetSymbolAddress((void**)&eaperm, g_eaperm);
    cudaGetSymbolAddress((void**)&sums, g_sums);
    cudaGetSymbolAddress((void**)&cnts, g_cnts);

    // ---- CSR build ----
    count_kernel<<<(EE + 255) / 256, 256>>>(ei, cnt);
    scan_kernel<<<1, 1024>>>(cnt, rowptr, cursor);
    scatter_kernel<<<(EE + 255) / 256, 256>>>(ei, ea, cursor, srcperm, eaperm);

    // ---- 4 fused layers ----
    const int blocks = NN / 4 / 8;  // 3125
    float* bufs[2] = {buf0, buf1};
    const float* cur = x;
    for (int l = 0; l < 3; l++) {
        float* nxt = bufs[l & 1];
        layer_kernel<false><<<blocks, 256>>>(
            cur, rowptr, srcperm, eaperm,
            lin_e + (size_t)l * 16 * 64,
            W1 + (size_t)l * 64 * 64, b1 + (size_t)l * 64,
            W2 + (size_t)l * 64 * 64, b2 + (size_t)l * 64,
            eps, l, nxt, batch, sums, cnts);
        cur = nxt;
    }
    layer_kernel<true><<<blocks, 256>>>(
        cur, rowptr, srcperm, eaperm,
        lin_e + (size_t)3 * 16 * 64,
        W1 + (size_t)3 * 64 * 64, b1 + (size_t)3 * 64,
        W2 + (size_t)3 * 64 * 64, b2 + (size_t)3 * 64,
        eps, 3, nullptr, batch, sums, cnts);

    head_kernel<<<(GG + 7) / 8, 256>>>(sums, cnts, t_cond, hW1, hb1, hW2, hb2, out);
}

// round 16
// speedup vs baseline: 1.1021x; 1.0161x over previous
#include <cuda_runtime.h>

#define NN 100000
#define EE 1000000
#define GG 2000

// ---------------- scratch (device globals; no allocation allowed) ----------
__device__ float g_buf0[NN * 64];
__device__ float g_buf1[NN * 64];
__device__ int   g_rowptr[NN + 1];
__device__ int   g_cnt[NN];       // zero-init at load; cleanup re-zeros
__device__ int   g_cursor[NN];
__device__ int   g_srcperm[EE];
__device__ float g_eaperm[EE * 16];
__device__ float g_sums[GG * 64]; // zero-init at load; cleanup re-zeros
__device__ float g_cnts[GG];      // zero-init at load; cleanup re-zeros

typedef unsigned long long ull;

__device__ __forceinline__ ull pack2(float a, float b) {
    ull r; asm("mov.b64 %0, {%1,%2};" : "=l"(r) : "f"(a), "f"(b)); return r;
}
__device__ __forceinline__ void unpack2(ull v, float& a, float& b) {
    asm("mov.b64 {%0,%1}, %2;" : "=f"(a), "=f"(b) : "l"(v));
}
__device__ __forceinline__ void ffma2(ull& d, ull a, ull b) {
    asm("fma.rn.f32x2 %0, %1, %2, %0;" : "+l"(d) : "l"(a), "l"(b));
}
__device__ __forceinline__ void red2(float* p, float x, float y) {
    asm volatile("red.global.add.v2.f32 [%0], {%1,%2};"
                 :: "l"(p), "f"(x), "f"(y) : "memory");
}
__device__ __forceinline__ unsigned smem_u32(const void* p) {
    unsigned a;
    asm("{ .reg .u64 t; cvta.to.shared.u64 t, %1; cvt.u32.u64 %0, t; }"
        : "=r"(a) : "l"(p));
    return a;
}
#define CP_ASYNC16(saddr, gptr) \
    asm volatile("cp.async.cg.shared.global [%0], [%1], 16;" \
                 :: "r"(saddr), "l"(gptr) : "memory")
#define CP_COMMIT() asm volatile("cp.async.commit_group;" ::: "memory")
#define CP_WAIT1()  asm volatile("cp.async.wait_group 1;" ::: "memory")

// ============================ CSR build =====================================
__global__ void __launch_bounds__(256) count_kernel(const int* __restrict__ ei,
                                                    int* __restrict__ cnt) {
    int e = blockIdx.x * blockDim.x + threadIdx.x;
    if (e < EE) atomicAdd(&cnt[ei[EE + e]], 1);
}

__global__ void __launch_bounds__(1024) scan_kernel(const int* __restrict__ cnt,
                                                    int* __restrict__ rowptr,
                                                    int* __restrict__ cursor) {
    const int CH = 100;
    int tid = threadIdx.x;
    int base = tid * CH;
    int s = 0;
    for (int i = 0; i < CH; i += 4) {
        int idx = base + i;
        if (idx + 3 < NN) {
            int4 v = *(const int4*)(cnt + idx);
            s += v.x + v.y + v.z + v.w;
        } else {
            for (int t = 0; t < 4; t++)
                if (idx + t < NN) s += cnt[idx + t];
        }
    }
    __shared__ int sh[1024];
    sh[tid] = s;
    __syncthreads();
    for (int off = 1; off < 1024; off <<= 1) {
        int v = (tid >= off) ? sh[tid - off] : 0;
        __syncthreads();
        sh[tid] += v;
        __syncthreads();
    }
    int run = sh[tid] - s;
    for (int i = 0; i < CH; i += 4) {
        int idx = base + i;
        if (idx + 3 < NN) {
            int4 c = *(const int4*)(cnt + idx);
            int4 rp;
            rp.x = run;
            rp.y = run + c.x;
            rp.z = rp.y + c.y;
            rp.w = rp.z + c.z;
            *(int4*)(rowptr + idx) = rp;
            *(int4*)(cursor + idx) = rp;
            run = rp.w + c.w;
        } else {
            for (int t = 0; t < 4; t++) {
                int k2 = idx + t;
                if (k2 < NN) { rowptr[k2] = run; cursor[k2] = run; run += cnt[k2]; }
            }
        }
    }
    if (NN >= base && NN < base + CH) rowptr[NN] = run;
}

__global__ void __launch_bounds__(256) scatter_kernel(const int* __restrict__ ei,
                                                      const float* __restrict__ ea,
                                                      int* __restrict__ cursor,
                                                      int* __restrict__ srcperm,
                                                      float* __restrict__ eaperm) {
    int e = blockIdx.x * blockDim.x + threadIdx.x;
    if (e < EE) {
        int d = ei[EE + e];
        int pos = atomicAdd(&cursor[d], 1);
        srcperm[pos] = ei[e];
        const float4* src = (const float4*)(ea + (size_t)e * 16);
        float4* dst = (float4*)(eaperm + (size_t)pos * 16);
        float4 v0 = src[0], v1 = src[1], v2 = src[2], v3 = src[3];
        dst[0] = v0; dst[1] = v1; dst[2] = v2; dst[3] = v3;
    }
}

// ============================ fused layer ===================================
// R10 edge loop (measured best: 8-edge chunks, 2-buffer cp.async staging of
// edge features, in-loop srcperm LDG + shfl, batched x gathers), with the
// group prologue (rowptr loads + chunk-0 ea staging) hoisted BEFORE the MLP
// weight staging so its DRAM latency overlaps the weight loads + syncthreads.
template <bool LAST>
__global__ void __launch_bounds__(256, 3) layer_kernel(
    const float* __restrict__ x,
    const int* __restrict__ rowptr, const int* __restrict__ srcperm,
    const float* __restrict__ eaperm,
    const float* __restrict__ line,
    const float* __restrict__ W1, const float* __restrict__ b1,
    const float* __restrict__ W2, const float* __restrict__ b2,
    const float* __restrict__ epsp, int l,
    float* __restrict__ xout,
    const int* __restrict__ batch,
    float* __restrict__ sums, float* __restrict__ cnts)
{
    __shared__ ulonglong2 W1v[32 * 32];     // 16 KB
    __shared__ ulonglong2 W2v[32 * 32];     // 16 KB
    __shared__ ull hdup[8][4][32];          //  8 KB
    __shared__ ulonglong2 easm[8][2][32];   //  8 KB : [warp][buf][8 edges x 4 qwords]

    const int lane = threadIdx.x & 31;
    const int wib  = threadIdx.x >> 5;
    const int warp = (blockIdx.x * 256 + threadIdx.x) >> 5;
    const int n0 = warp * 4;

    // ---- group prologue FIRST: DRAM latency hides under weight staging ----
    const int r0   = rowptr[n0];
    const int bnd1 = rowptr[n0 + 1];
    const int bnd2 = rowptr[n0 + 2];
    const int bnd3 = rowptr[n0 + 3];
    const int r4   = rowptr[n0 + 4];

    const char* eab = (const char*)eaperm;
    const unsigned easm_base = smem_u32(&easm[wib][0][0]) + lane * 16u;

    int cb = r0;
    int cnt = min(8, r4 - cb);

    // stage chunk 0 into buf 0 (64B-aligned global source: cb*64)
    if (cnt > 0 && lane < cnt * 4)
        CP_ASYNC16(easm_base, eab + (size_t)cb * 64 + lane * 16);
    CP_COMMIT();

    // ---- weight staging (overlaps the prologue copies) ----
    for (int i = threadIdx.x; i < 32 * 32; i += 256) {
        int kk = i >> 5, ln = i & 31;
        W1v[i] = make_ulonglong2(
            pack2(W1[(2 * kk) * 64 + 2 * ln],     W1[(2 * kk + 1) * 64 + 2 * ln]),
            pack2(W1[(2 * kk) * 64 + 2 * ln + 1], W1[(2 * kk + 1) * 64 + 2 * ln + 1]));
        W2v[i] = make_ulonglong2(
            pack2(W2[(2 * kk) * 64 + 2 * ln],     W2[(2 * kk + 1) * 64 + 2 * ln]),
            pack2(W2[(2 * kk) * 64 + 2 * ln + 1], W2[(2 * kk + 1) * 64 + 2 * ln + 1]));
    }

    // Edge weights as k-pairs: wP for dim 2*lane, wQ for dim 2*lane+1.
    ull wP[8], wQ[8];
#pragma unroll
    for (int k = 0; k < 8; k++) {
        wP[k] = pack2(line[(2 * k) * 64 + 2 * lane],     line[(2 * k + 1) * 64 + 2 * lane]);
        wQ[k] = pack2(line[(2 * k) * 64 + 2 * lane + 1], line[(2 * k + 1) * 64 + 2 * lane + 1]);
    }
    const float epsv = 1.0f + epsp[l];
    __syncthreads();

    int j = 0;
    int bnext = bnd1;
    float a0 = 0.f, a1 = 0.f;

    int buf = 0;
    while (cnt > 0) {
        // current chunk's src indices (overlaps with staging wait)
        int adr = cb + lane;
        adr = adr < r4 ? adr : r4 - 1;
        int sreg = __ldg(srcperm + adr);

        // prefetch chunk cb+8 into the other buffer (no registers consumed)
        const int cnt_n = min(8, r4 - (cb + 8));
        if (cnt_n > 0 && lane < cnt_n * 4)
            CP_ASYNC16(easm_base + (buf ^ 1) * 512u,
                       eab + (size_t)(cb + 8) * 64 + lane * 16);
        CP_COMMIT();

        CP_WAIT1();     // current buf's copies complete (next chunk may pend)
        __syncwarp();   // make all lanes' copies visible

        // batched x gathers for the current chunk
        float2 xv[8];
#pragma unroll
        for (int t = 0; t < 8; t++) {
            int st = __shfl_sync(0xFFFFFFFFu, sreg, t);
            if (t < cnt)
                xv[t] = __ldg((const float2*)(x + (size_t)st * 64 + lane * 2));
        }

        // compute 8 edges from easm[wib][buf]
#pragma unroll
        for (int t = 0; t < 8; t++) {
            if (t >= cnt) break;                 // warp-uniform
            const int p = cb + t;
            while (p >= bnext) {                 // warp-uniform, rare
                float2 xs = *(const float2*)(x + (size_t)(n0 + j) * 64 + lane * 2);
                hdup[wib][j][lane] = pack2(fmaf(epsv, xs.x, a0), fmaf(epsv, xs.y, a1));
                a0 = 0.f; a1 = 0.f;
                j++;
                bnext = (j == 1) ? bnd2 : (j == 2) ? bnd3 : r4;
            }
            ulonglong2 E0 = easm[wib][buf][4 * t + 0];
            ulonglong2 E1 = easm[wib][buf][4 * t + 1];
            ulonglong2 E2 = easm[wib][buf][4 * t + 2];
            ulonglong2 E3 = easm[wib][buf][4 * t + 3];
            ull acP = 0ull, acQ = 0ull;
            ffma2(acP, E0.x, wP[0]); ffma2(acQ, E0.x, wQ[0]);
            ffma2(acP, E0.y, wP[1]); ffma2(acQ, E0.y, wQ[1]);
            ffma2(acP, E1.x, wP[2]); ffma2(acQ, E1.x, wQ[2]);
            ffma2(acP, E1.y, wP[3]); ffma2(acQ, E1.y, wQ[3]);
            ffma2(acP, E2.x, wP[4]); ffma2(acQ, E2.x, wQ[4]);
            ffma2(acP, E2.y, wP[5]); ffma2(acQ, E2.y, wQ[5]);
            ffma2(acP, E3.x, wP[6]); ffma2(acQ, E3.x, wQ[6]);
            ffma2(acP, E3.y, wP[7]); ffma2(acQ, E3.y, wQ[7]);
            float pa, pb, qa, qb;
            unpack2(acP, pa, pb);
            unpack2(acQ, qa, qb);
            float m0 = (pa + xv[t].x) + pb;
            float m1 = (qa + xv[t].y) + qb;
            a0 += fmaxf(m0, 0.f);
            a1 += fmaxf(m1, 0.f);
        }
        __syncwarp();   // all lanes done reading buf before it is re-staged

        buf ^= 1;
        cb += 8;
        cnt = cnt_n;
    }
    while (j < 4) {   // flush remaining nodes (incl. zero-degree)
        float2 xs = *(const float2*)(x + (size_t)(n0 + j) * 64 + lane * 2);
        hdup[wib][j][lane] = pack2(fmaf(epsv, xs.x, a0), fmaf(epsv, xs.y, a1));
        a0 = 0.f; a1 = 0.f;
        j++;
    }
    __syncwarp();

    const float b1v0 = b1[2 * lane], b1v1 = b1[2 * lane + 1];
    const float b2v0 = b2[2 * lane], b2v1 = b2[2 * lane + 1];

    // ---- MLP matmul 1 (bias folded into acc.lo) ----
    ull accP[4], accQ[4];
#pragma unroll
    for (int jj = 0; jj < 4; jj++) {
        accP[jj] = pack2(b1v0, 0.f);
        accQ[jj] = pack2(b1v1, 0.f);
    }
#pragma unroll 8
    for (int kk = 0; kk < 32; kk++) {
        ulonglong2 wv = W1v[kk * 32 + lane];
#pragma unroll
        for (int jj = 0; jj < 4; jj++) {
            ull hp = hdup[wib][jj][kk];
            ffma2(accP[jj], hp, wv.x);
            ffma2(accQ[jj], hp, wv.y);
        }
    }
    __syncwarp();
#pragma unroll
    for (int jj = 0; jj < 4; jj++) {
        float pa, pb, qa, qb;
        unpack2(accP[jj], pa, pb);
        unpack2(accQ[jj], qa, qb);
        float y0 = fmaxf(pa + pb, 0.f);
        float y1 = fmaxf(qa + qb, 0.f);
        hdup[wib][jj][lane] = pack2(y0, y1);
        accP[jj] = pack2(b2v0, 0.f);
        accQ[jj] = pack2(b2v1, 0.f);
    }
    __syncwarp();

    // ---- MLP matmul 2 ----
#pragma unroll 8
    for (int kk = 0; kk < 32; kk++) {
        ulonglong2 wv = W2v[kk * 32 + lane];
#pragma unroll
        for (int jj = 0; jj < 4; jj++) {
            ull hp = hdup[wib][jj][kk];
            ffma2(accP[jj], hp, wv.x);
            ffma2(accQ[jj], hp, wv.y);
        }
    }

#pragma unroll
    for (int jj = 0; jj < 4; jj++) {
        float pa, pb, qa, qb;
        unpack2(accP[jj], pa, pb);
        unpack2(accQ[jj], qa, qb);
        float y0 = fmaxf(pa + pb, 0.f);
        float y1 = fmaxf(qa + qb, 0.f);
        if (!LAST) {
            *(float2*)(xout + (size_t)(n0 + jj) * 64 + lane * 2) = make_float2(y0, y1);
        } else {
            int g = batch[n0 + jj];
            red2(sums + (size_t)g * 64 + lane * 2, y0, y1);
            if (lane == 0) atomicAdd(cnts + g, 1.0f);
        }
    }
}

// ============================ head ==========================================
__global__ void __launch_bounds__(256) head_kernel(
    const float* __restrict__ sums, const float* __restrict__ cnts,
    const float* __restrict__ t_cond,
    const float* __restrict__ hW1, const float* __restrict__ hb1,
    const float* __restrict__ hW2, const float* __restrict__ hb2,
    float* __restrict__ out)
{
    const int lane = threadIdx.x & 31;
    const int g    = (blockIdx.x * blockDim.x + threadIdx.x) >> 5;
    if (g >= GG) return;

    float c  = fmaxf(cnts[g], 1.0f);
    float p0 = sums[(size_t)g * 64 + lane] / c;
    float p1 = sums[(size_t)g * 64 + lane + 32] / c;

    float acc0 = hb1[lane], acc1 = hb1[lane + 32];
    for (int k = 0; k < 32; k++) {
        float a = __shfl_sync(0xFFFFFFFFu, p0, k);
        acc0 = fmaf(a, hW1[k * 64 + lane],      acc0);
        acc1 = fmaf(a, hW1[k * 64 + lane + 32], acc1);
    }
    for (int k = 0; k < 32; k++) {
        float a = __shfl_sync(0xFFFFFFFFu, p1, k);
        acc0 = fmaf(a, hW1[(k + 32) * 64 + lane],      acc0);
        acc1 = fmaf(a, hW1[(k + 32) * 64 + lane + 32], acc1);
    }
    float t = t_cond[g];
    acc0 = fmaf(t, hW1[64 * 64 + lane],      acc0);
    acc1 = fmaf(t, hW1[64 * 64 + lane + 32], acc1);

    acc0 = fmaxf(acc0, 0.f);
    acc1 = fmaxf(acc1, 0.f);

    float r = acc0 * hW2[lane] + acc1 * hW2[lane + 32];
#pragma unroll
    for (int o = 16; o; o >>= 1) r += __shfl_xor_sync(0xFFFFFFFFu, r, o);
    if (lane == 0) out[g] = r + hb2[0];
}

// Trailing cleanup: re-zero accumulators for the next execution.
__global__ void __launch_bounds__(256) cleanup_kernel(int* __restrict__ cnt,
                                                      float* __restrict__ sums,
                                                      float* __restrict__ cnts) {
    int i = blockIdx.x * blockDim.x + threadIdx.x;
    if (i < NN) cnt[i] = 0;
    if (i < GG * 64) sums[i] = 0.f;
    if (i < GG) cnts[i] = 0.f;
}

// ============================================================================
extern "C" void kernel_launch(void* const* d_in, const int* in_sizes, int n_in,
                              void* d_out, int out_size)
{
    const float* x      = (const float*)d_in[0];
    const int*   ei     = (const int*)  d_in[1];
    const float* ea     = (const float*)d_in[2];
    const int*   batch  = (const int*)  d_in[3];
    const float* t_cond = (const float*)d_in[4];
    const float* lin_e  = (const float*)d_in[5];
    const float* W1     = (const float*)d_in[6];
    const float* b1     = (const float*)d_in[7];
    const float* W2     = (const float*)d_in[8];
    const float* b2     = (const float*)d_in[9];
    const float* eps    = (const float*)d_in[10];
    const float* hW1    = (const float*)d_in[11];
    const float* hb1    = (const float*)d_in[12];
    const float* hW2    = (const float*)d_in[13];
    const float* hb2    = (const float*)d_in[14];
    float* out = (float*)d_out;

    float *buf0, *buf1, *eaperm, *sums, *cnts;
    int *rowptr, *cnt, *cursor, *srcperm;
    cudaGetSymbolAddress((void**)&buf0, g_buf0);
    cudaGetSymbolAddress((void**)&buf1, g_buf1);
    cudaGetSymbolAddress((void**)&rowptr, g_rowptr);
    cudaGetSymbolAddress((void**)&cnt, g_cnt);
    cudaGetSymbolAddress((void**)&cursor, g_cursor);
    cudaGetSymbolAddress((void**)&srcperm, g_srcperm);
    cudaGetSymbolAddress((void**)&eaperm, g_eaperm);
    cudaGetSymbolAddress((void**)&sums, g_sums);
    cudaGetSymbolAddress((void**)&cnts, g_cnts);

    // ---- CSR build ----
    count_kernel<<<(EE + 255) / 256, 256>>>(ei, cnt);
    scan_kernel<<<1, 1024>>>(cnt, rowptr, cursor);
    scatter_kernel<<<(EE + 255) / 256, 256>>>(ei, ea, cursor, srcperm, eaperm);

    // ---- 4 fused layers ----
    const int blocks = NN / 4 / 8;  // 3125
    float* bufs[2] = {buf0, buf1};
    const float* cur = x;
    for (int l = 0; l < 3; l++) {
        float* nxt = bufs[l & 1];
        layer_kernel<false><<<blocks, 256>>>(
            cur, rowptr, srcperm, eaperm,
            lin_e + (size_t)l * 16 * 64,
            W1 + (size_t)l * 64 * 64, b1 + (size_t)l * 64,
            W2 + (size_t)l * 64 * 64, b2 + (size_t)l * 64,
            eps, l, nxt, batch, sums, cnts);
        cur = nxt;
    }
    layer_kernel<true><<<blocks, 256>>>(
        cur, rowptr, srcperm, eaperm,
        lin_e + (size_t)3 * 16 * 64,
        W1 + (size_t)3 * 64 * 64, b1 + (size_t)3 * 64,
        W2 + (size_t)3 * 64 * 64, b2 + (size_t)3 * 64,
        eps, 3, nullptr, batch, sums, cnts);

    head_kernel<<<(GG + 7) / 8, 256>>>(sums, cnts, t_cond, hW1, hb1, hW2, hb2, out);
    cleanup_kernel<<<(GG * 64 + 255) / 256, 256>>>(cnt, sums, cnts);
}

// round 17
// speedup vs baseline: 1.1341x; 1.0291x over previous
#include <cuda_runtime.h>

#define NN 100000
#define EE 1000000
#define GG 2000

// ---------------- scratch (device globals; no allocation allowed) ----------
__device__ float g_buf0[NN * 64];
__device__ float g_buf1[NN * 64];
__device__ int   g_rowptr[NN + 1];
__device__ int   g_cnt[NN];       // zero-init at load; cleanup re-zeros
__device__ int   g_rank[EE];      // per-edge rank within its destination
__device__ int   g_srcperm[EE];
__device__ float g_eaperm[EE * 16];
__device__ float g_sums[GG * 64]; // zero-init at load; cleanup re-zeros
__device__ float g_cnts[GG];      // zero-init at load; cleanup re-zeros

typedef unsigned long long ull;

__device__ __forceinline__ ull pack2(float a, float b) {
    ull r; asm("mov.b64 %0, {%1,%2};" : "=l"(r) : "f"(a), "f"(b)); return r;
}
__device__ __forceinline__ void unpack2(ull v, float& a, float& b) {
    asm("mov.b64 {%0,%1}, %2;" : "=f"(a), "=f"(b) : "l"(v));
}
__device__ __forceinline__ void ffma2(ull& d, ull a, ull b) {
    asm("fma.rn.f32x2 %0, %1, %2, %0;" : "+l"(d) : "l"(a), "l"(b));
}
__device__ __forceinline__ void red2(float* p, float x, float y) {
    asm volatile("red.global.add.v2.f32 [%0], {%1,%2};"
                 :: "l"(p), "f"(x), "f"(y) : "memory");
}
__device__ __forceinline__ unsigned smem_u32(const void* p) {
    unsigned a;
    asm("{ .reg .u64 t; cvta.to.shared.u64 t, %1; cvt.u32.u64 %0, t; }"
        : "=r"(a) : "l"(p));
    return a;
}
#define CP_ASYNC16(saddr, gptr) \
    asm volatile("cp.async.cg.shared.global [%0], [%1], 16;" \
                 :: "r"(saddr), "l"(gptr) : "memory")
#define CP_COMMIT() asm volatile("cp.async.commit_group;" ::: "memory")
#define CP_WAIT1()  asm volatile("cp.async.wait_group 1;" ::: "memory")

// ============================ CSR build =====================================
// count also records each edge's arrival rank (atomicAdd return value),
// so scatter needs no atomic: pos = rowptr[dst] + rank[e].
__global__ void __launch_bounds__(256) count_kernel(const int* __restrict__ ei,
                                                    int* __restrict__ cnt,
                                                    int* __restrict__ rank) {
    int e = blockIdx.x * blockDim.x + threadIdx.x;
    if (e < EE) rank[e] = atomicAdd(&cnt[ei[EE + e]], 1);
}

__global__ void __launch_bounds__(1024) scan_kernel(const int* __restrict__ cnt,
                                                    int* __restrict__ rowptr) {
    const int CH = 100;
    int tid = threadIdx.x;
    int base = tid * CH;
    int s = 0;
    for (int i = 0; i < CH; i += 4) {
        int idx = base + i;
        if (idx + 3 < NN) {
            int4 v = *(const int4*)(cnt + idx);
            s += v.x + v.y + v.z + v.w;
        } else {
            for (int t = 0; t < 4; t++)
                if (idx + t < NN) s += cnt[idx + t];
        }
    }
    __shared__ int sh[1024];
    sh[tid] = s;
    __syncthreads();
    for (int off = 1; off < 1024; off <<= 1) {
        int v = (tid >= off) ? sh[tid - off] : 0;
        __syncthreads();
        sh[tid] += v;
        __syncthreads();
    }
    int run = sh[tid] - s;
    for (int i = 0; i < CH; i += 4) {
        int idx = base + i;
        if (idx + 3 < NN) {
            int4 c = *(const int4*)(cnt + idx);
            int4 rp;
            rp.x = run;
            rp.y = run + c.x;
            rp.z = rp.y + c.y;
            rp.w = rp.z + c.z;
            *(int4*)(rowptr + idx) = rp;
            run = rp.w + c.w;
        } else {
            for (int t = 0; t < 4; t++) {
                int k2 = idx + t;
                if (k2 < NN) { rowptr[k2] = run; run += cnt[k2]; }
            }
        }
    }
    if (NN >= base && NN < base + CH) rowptr[NN] = run;
}

// Atomic-free scatter: pos = rowptr[dst] + rank[e].
__global__ void __launch_bounds__(256) scatter_kernel(const int* __restrict__ ei,
                                                      const float* __restrict__ ea,
                                                      const int* __restrict__ rowptr,
                                                      const int* __restrict__ rank,
                                                      int* __restrict__ srcperm,
                                                      float* __restrict__ eaperm) {
    int e = blockIdx.x * blockDim.x + threadIdx.x;
    if (e < EE) {
        int d = ei[EE + e];
        int pos = __ldg(rowptr + d) + rank[e];
        srcperm[pos] = ei[e];
        const float4* src = (const float4*)(ea + (size_t)e * 16);
        float4* dst = (float4*)(eaperm + (size_t)pos * 16);
        float4 v0 = src[0], v1 = src[1], v2 = src[2], v3 = src[3];
        dst[0] = v0; dst[1] = v1; dst[2] = v2; dst[3] = v3;
    }
}

// ============================ fused layer ===================================
// Measured-best configuration (R10/R16): 8-edge chunks, 2-buffer cp.async
// staging of edge features, in-loop srcperm LDG + shfl, batched x gathers,
// group prologue hoisted before MLP weight staging.
template <bool LAST>
__global__ void __launch_bounds__(256, 3) layer_kernel(
    const float* __restrict__ x,
    const int* __restrict__ rowptr, const int* __restrict__ srcperm,
    const float* __restrict__ eaperm,
    const float* __restrict__ line,
    const float* __restrict__ W1, const float* __restrict__ b1,
    const float* __restrict__ W2, const float* __restrict__ b2,
    const float* __restrict__ epsp, int l,
    float* __restrict__ xout,
    const int* __restrict__ batch,
    float* __restrict__ sums, float* __restrict__ cnts)
{
    __shared__ ulonglong2 W1v[32 * 32];     // 16 KB
    __shared__ ulonglong2 W2v[32 * 32];     // 16 KB
    __shared__ ull hdup[8][4][32];          //  8 KB
    __shared__ ulonglong2 easm[8][2][32];   //  8 KB : [warp][buf][8 edges x 4 qwords]

    const int lane = threadIdx.x & 31;
    const int wib  = threadIdx.x >> 5;
    const int warp = (blockIdx.x * 256 + threadIdx.x) >> 5;
    const int n0 = warp * 4;

    // ---- group prologue FIRST: DRAM latency hides under weight staging ----
    const int r0   = rowptr[n0];
    const int bnd1 = rowptr[n0 + 1];
    const int bnd2 = rowptr[n0 + 2];
    const int bnd3 = rowptr[n0 + 3];
    const int r4   = rowptr[n0 + 4];

    const char* eab = (const char*)eaperm;
    const unsigned easm_base = smem_u32(&easm[wib][0][0]) + lane * 16u;

    int cb = r0;
    int cnt = min(8, r4 - cb);

    // stage chunk 0 into buf 0 (64B-aligned global source: cb*64)
    if (cnt > 0 && lane < cnt * 4)
        CP_ASYNC16(easm_base, eab + (size_t)cb * 64 + lane * 16);
    CP_COMMIT();

    // ---- weight staging (vectorized float2 reads; overlaps prologue) ----
    for (int i = threadIdx.x; i < 32 * 32; i += 256) {
        int kk = i >> 5, ln = i & 31;
        float2 a1 = *(const float2*)(W1 + (2 * kk) * 64 + 2 * ln);
        float2 c1 = *(const float2*)(W1 + (2 * kk + 1) * 64 + 2 * ln);
        W1v[i] = make_ulonglong2(pack2(a1.x, c1.x), pack2(a1.y, c1.y));
        float2 a2 = *(const float2*)(W2 + (2 * kk) * 64 + 2 * ln);
        float2 c2 = *(const float2*)(W2 + (2 * kk + 1) * 64 + 2 * ln);
        W2v[i] = make_ulonglong2(pack2(a2.x, c2.x), pack2(a2.y, c2.y));
    }

    // Edge weights as k-pairs: wP for dim 2*lane, wQ for dim 2*lane+1.
    ull wP[8], wQ[8];
#pragma unroll
    for (int k = 0; k < 8; k++) {
        wP[k] = pack2(line[(2 * k) * 64 + 2 * lane],     line[(2 * k + 1) * 64 + 2 * lane]);
        wQ[k] = pack2(line[(2 * k) * 64 + 2 * lane + 1], line[(2 * k + 1) * 64 + 2 * lane + 1]);
    }
    const float epsv = 1.0f + epsp[l];
    __syncthreads();

    int j = 0;
    int bnext = bnd1;
    float a0 = 0.f, a1 = 0.f;

    int buf = 0;
    while (cnt > 0) {
        // current chunk's src indices (overlaps with staging wait)
        int adr = cb + lane;
        adr = adr < r4 ? adr : r4 - 1;
        int sreg = __ldg(srcperm + adr);

        // prefetch chunk cb+8 into the other buffer (no registers consumed)
        const int cnt_n = min(8, r4 - (cb + 8));
        if (cnt_n > 0 && lane < cnt_n * 4)
            CP_ASYNC16(easm_base + (buf ^ 1) * 512u,
                       eab + (size_t)(cb + 8) * 64 + lane * 16);
        CP_COMMIT();

        CP_WAIT1();     // current buf's copies complete (next chunk may pend)
        __syncwarp();   // make all lanes' copies visible

        // batched x gathers for the current chunk
        float2 xv[8];
#pragma unroll
        for (int t = 0; t < 8; t++) {
            int st = __shfl_sync(0xFFFFFFFFu, sreg, t);
            if (t < cnt)
                xv[t] = __ldg((const float2*)(x + (size_t)st * 64 + lane * 2));
        }

        // compute 8 edges from easm[wib][buf]
#pragma unroll
        for (int t = 0; t < 8; t++) {
            if (t >= cnt) break;                 // warp-uniform
            const int p = cb + t;
            while (p >= bnext) {                 // warp-uniform, rare
                float2 xs = *(const float2*)(x + (size_t)(n0 + j) * 64 + lane * 2);
                hdup[wib][j][lane] = pack2(fmaf(epsv, xs.x, a0), fmaf(epsv, xs.y, a1));
                a0 = 0.f; a1 = 0.f;
                j++;
                bnext = (j == 1) ? bnd2 : (j == 2) ? bnd3 : r4;
            }
            ulonglong2 E0 = easm[wib][buf][4 * t + 0];
            ulonglong2 E1 = easm[wib][buf][4 * t + 1];
            ulonglong2 E2 = easm[wib][buf][4 * t + 2];
            ulonglong2 E3 = easm[wib][buf][4 * t + 3];
            ull acP = 0ull, acQ = 0ull;
            ffma2(acP, E0.x, wP[0]); ffma2(acQ, E0.x, wQ[0]);
            ffma2(acP, E0.y, wP[1]); ffma2(acQ, E0.y, wQ[1]);
            ffma2(acP, E1.x, wP[2]); ffma2(acQ, E1.x, wQ[2]);
            ffma2(acP, E1.y, wP[3]); ffma2(acQ, E1.y, wQ[3]);
            ffma2(acP, E2.x, wP[4]); ffma2(acQ, E2.x, wQ[4]);
            ffma2(acP, E2.y, wP[5]); ffma2(acQ, E2.y, wQ[5]);
            ffma2(acP, E3.x, wP[6]); ffma2(acQ, E3.x, wQ[6]);
            ffma2(acP, E3.y, wP[7]); ffma2(acQ, E3.y, wQ[7]);
            float pa, pb, qa, qb;
            unpack2(acP, pa, pb);
            unpack2(acQ, qa, qb);
            float m0 = (pa + xv[t].x) + pb;
            float m1 = (qa + xv[t].y) + qb;
            a0 += fmaxf(m0, 0.f);
            a1 += fmaxf(m1, 0.f);
        }
        __syncwarp();   // all lanes done reading buf before it is re-staged

        buf ^= 1;
        cb += 8;
        cnt = cnt_n;
    }
    while (j < 4) {   // flush remaining nodes (incl. zero-degree)
        float2 xs = *(const float2*)(x + (size_t)(n0 + j) * 64 + lane * 2);
        hdup[wib][j][lane] = pack2(fmaf(epsv, xs.x, a0), fmaf(epsv, xs.y, a1));
        a0 = 0.f; a1 = 0.f;
        j++;
    }
    __syncwarp();

    const float b1v0 = b1[2 * lane], b1v1 = b1[2 * lane + 1];
    const float b2v0 = b2[2 * lane], b2v1 = b2[2 * lane + 1];

    // ---- MLP matmul 1 (bias folded into acc.lo) ----
    ull accP[4], accQ[4];
#pragma unroll
    for (int jj = 0; jj < 4; jj++) {
        accP[jj] = pack2(b1v0, 0.f);
        accQ[jj] = pack2(b1v1, 0.f);
    }
#pragma unroll 8
    for (int kk = 0; kk < 32; kk++) {
        ulonglong2 wv = W1v[kk * 32 + lane];
#pragma unroll
        for (int jj = 0; jj < 4; jj++) {
            ull hp = hdup[wib][jj][kk];
            ffma2(accP[jj], hp, wv.x);
            ffma2(accQ[jj], hp, wv.y);
        }
    }
    __syncwarp();
#pragma unroll
    for (int jj = 0; jj < 4; jj++) {
        float pa, pb, qa, qb;
        unpack2(accP[jj], pa, pb);
        unpack2(accQ[jj], qa, qb);
        float y0 = fmaxf(pa + pb, 0.f);
        float y1 = fmaxf(qa + qb, 0.f);
        hdup[wib][jj][lane] = pack2(y0, y1);
        accP[jj] = pack2(b2v0, 0.f);
        accQ[jj] = pack2(b2v1, 0.f);
    }
    __syncwarp();

    // ---- MLP matmul 2 ----
#pragma unroll 8
    for (int kk = 0; kk < 32; kk++) {
        ulonglong2 wv = W2v[kk * 32 + lane];
#pragma unroll
        for (int jj = 0; jj < 4; jj++) {
            ull hp = hdup[wib][jj][kk];
            ffma2(accP[jj], hp, wv.x);
            ffma2(accQ[jj], hp, wv.y);
        }
    }

#pragma unroll
    for (int jj = 0; jj < 4; jj++) {
        float pa, pb, qa, qb;
        unpack2(accP[jj], pa, pb);
        unpack2(accQ[jj], qa, qb);
        float y0 = fmaxf(pa + pb, 0.f);
        float y1 = fmaxf(qa + qb, 0.f);
        if (!LAST) {
            *(float2*)(xout + (size_t)(n0 + jj) * 64 + lane * 2) = make_float2(y0, y1);
        } else {
            int g = batch[n0 + jj];
            red2(sums + (size_t)g * 64 + lane * 2, y0, y1);
            if (lane == 0) atomicAdd(cnts + g, 1.0f);
        }
    }
}

// ============================ head ==========================================
__global__ void __launch_bounds__(256) head_kernel(
    const float* __restrict__ sums, const float* __restrict__ cnts,
    const float* __restrict__ t_cond,
    const float* __restrict__ hW1, const float* __restrict__ hb1,
    const float* __restrict__ hW2, const float* __restrict__ hb2,
    float* __restrict__ out)
{
    const int lane = threadIdx.x & 31;
    const int g    = (blockIdx.x * blockDim.x + threadIdx.x) >> 5;
    if (g >= GG) return;

    float c  = fmaxf(cnts[g], 1.0f);
    float p0 = sums[(size_t)g * 64 + lane] / c;
    float p1 = sums[(size_t)g * 64 + lane + 32] / c;

    float acc0 = hb1[lane], acc1 = hb1[lane + 32];
    for (int k = 0; k < 32; k++) {
        float a = __shfl_sync(0xFFFFFFFFu, p0, k);
        acc0 = fmaf(a, hW1[k * 64 + lane],      acc0);
        acc1 = fmaf(a, hW1[k * 64 + lane + 32], acc1);
    }
    for (int k = 0; k < 32; k++) {
        float a = __shfl_sync(0xFFFFFFFFu, p1, k);
        acc0 = fmaf(a, hW1[(k + 32) * 64 + lane],      acc0);
        acc1 = fmaf(a, hW1[(k + 32) * 64 + lane + 32], acc1);
    }
    float t = t_cond[g];
    acc0 = fmaf(t, hW1[64 * 64 + lane],      acc0);
    acc1 = fmaf(t, hW1[64 * 64 + lane + 32], acc1);

    acc0 = fmaxf(acc0, 0.f);
    acc1 = fmaxf(acc1, 0.f);

    float r = acc0 * hW2[lane] + acc1 * hW2[lane + 32];
#pragma unroll
    for (int o = 16; o; o >>= 1) r += __shfl_xor_sync(0xFFFFFFFFu, r, o);
    if (lane == 0) out[g] = r + hb2[0];
}

// Trailing cleanup: re-zero accumulators for the next execution.
__global__ void __launch_bounds__(256) cleanup_kernel(int* __restrict__ cnt,
                                                      float* __restrict__ sums,
                                                      float* __restrict__ cnts) {
    int i = blockIdx.x * blockDim.x + threadIdx.x;
    if (i < NN) cnt[i] = 0;
    if (i < GG * 64) sums[i] = 0.f;
    if (i < GG) cnts[i] = 0.f;
}

// ============================================================================
extern "C" void kernel_launch(void* const* d_in, const int* in_sizes, int n_in,
                              void* d_out, int out_size)
{
    const float* x      = (const float*)d_in[0];
    const int*   ei     = (const int*)  d_in[1];
    const float* ea     = (const float*)d_in[2];
    const int*   batch  = (const int*)  d_in[3];
    const float* t_cond = (const float*)d_in[4];
    const float* lin_e  = (const float*)d_in[5];
    const float* W1     = (const float*)d_in[6];
    const float* b1     = (const float*)d_in[7];
    const float* W2     = (const float*)d_in[8];
    const float* b2     = (const float*)d_in[9];
    const float* eps    = (const float*)d_in[10];
    const float* hW1    = (const float*)d_in[11];
    const float* hb1    = (const float*)d_in[12];
    const float* hW2    = (const float*)d_in[13];
    const float* hb2    = (const float*)d_in[14];
    float* out = (float*)d_out;

    float *buf0, *buf1, *eaperm, *sums, *cnts;
    int *rowptr, *cnt, *rank, *srcperm;
    cudaGetSymbolAddress((void**)&buf0, g_buf0);
    cudaGetSymbolAddress((void**)&buf1, g_buf1);
    cudaGetSymbolAddress((void**)&rowptr, g_rowptr);
    cudaGetSymbolAddress((void**)&cnt, g_cnt);
    cudaGetSymbolAddress((void**)&rank, g_rank);
    cudaGetSymbolAddress((void**)&srcperm, g_srcperm);
    cudaGetSymbolAddress((void**)&eaperm, g_eaperm);
    cudaGetSymbolAddress((void**)&sums, g_sums);
    cudaGetSymbolAddress((void**)&cnts, g_cnts);

    // ---- CSR build (rank-based, atomic-free scatter) ----
    count_kernel<<<(EE + 255) / 256, 256>>>(ei, cnt, rank);
    scan_kernel<<<1, 1024>>>(cnt, rowptr);
    scatter_kernel<<<(EE + 255) / 256, 256>>>(ei, ea, rowptr, rank, srcperm, eaperm);

    // ---- 4 fused layers ----
    const int blocks = NN / 4 / 8;  // 3125
    float* bufs[2] = {buf0, buf1};
    const float* cur = x;
    for (int l = 0; l < 3; l++) {
        float* nxt = bufs[l & 1];
        layer_kernel<false><<<blocks, 256>>>(
            cur, rowptr, srcperm, eaperm,
            lin_e + (size_t)l * 16 * 64,
            W1 + (size_t)l * 64 * 64, b1 + (size_t)l * 64,
            W2 + (size_t)l * 64 * 64, b2 + (size_t)l * 64,
            eps, l, nxt, batch, sums, cnts);
        cur = nxt;
    }
    layer_kernel<true><<<blocks, 256>>>(
        cur, rowptr, srcperm, eaperm,
        lin_e + (size_t)3 * 16 * 64,
        W1 + (size_t)3 * 64 * 64, b1 + (size_t)3 * 64,
        W2 + (size_t)3 * 64 * 64, b2 + (size_t)3 * 64,
        eps, 3, nullptr, batch, sums, cnts);

    head_kernel<<<(GG + 7) / 8, 256>>>(sums, cnts, t_cond, hW1, hb1, hW2, hb2, out);
    cleanup_kernel<<<(GG * 64 + 255) / 256, 256>>>(cnt, sums, cnts);
}